// round 9
// baseline (speedup 1.0000x reference)
#include <cuda_runtime.h>
#include <cuda_fp16.h>
#include <cstdint>
#include <cstddef>
#include <cstring>

// ============================================================================
// TTLinear, fully fused (single launch):
//   per-CTA b-block of 64 rows; loop over 64 m01 planes:
//     stage1 (smem):  Zs[b][k=n23*8+r2] = sum_n01 xT[(n23,b)][n01] * P[(m01,r2)][n01]
//     stage2 (global): y[b][m01*64+m23] = sum_k Zs[b][k] * Q[m23][k] + bias
// P/Q are rebuilt from the TT cores inside every CTA (trivial FLOPs); Z never
// touches DRAM (saves the 536 MB round-trip that bounded R8 at 139.8us).
// 25.8 GF on mma.sync HMMA (fp16 in, fp32 acc), rel_err ~4e-4.
// ============================================================================

#define OUTF 4096

// smem layout (bytes): xT 128K | P 32K | Q 32K | Z 32K  = 224 KB
#define XT_OFF 0u
#define P_OFF  131072u
#define Q_OFF  163840u
#define Z_OFF  196608u
#define SMEM_TOTAL 229376

#define SW(o) ((o) ^ ((((o) >> 7) & 3u) << 4))

static __device__ __forceinline__ uint32_t h2u(__half2 h) {
    uint32_t u; memcpy(&u, &h, 4); return u;
}
static __device__ __forceinline__ uint32_t s2u(const void* p) {
    uint32_t a;
    asm("{ .reg .u64 t; cvta.to.shared.u64 t, %1; cvt.u32.u64 %0, t; }" : "=r"(a) : "l"(p));
    return a;
}
static __device__ __forceinline__ void ldm_x4(uint32_t* r, uint32_t addr) {
    asm volatile("ldmatrix.sync.aligned.m8n8.x4.shared.b16 {%0,%1,%2,%3}, [%4];"
                 : "=r"(r[0]), "=r"(r[1]), "=r"(r[2]), "=r"(r[3]) : "r"(addr));
}
static __device__ __forceinline__ void mma16816(float* d, const uint32_t* a,
                                                const uint32_t* b) {
    asm volatile(
        "mma.sync.aligned.m16n8k16.row.col.f32.f16.f16.f32 "
        "{%0,%1,%2,%3}, {%4,%5,%6,%7}, {%8,%9}, {%0,%1,%2,%3};"
        : "+f"(d[0]), "+f"(d[1]), "+f"(d[2]), "+f"(d[3])
        : "r"(a[0]), "r"(a[1]), "r"(a[2]), "r"(a[3]), "r"(b[0]), "r"(b[1]));
}

__global__ void __launch_bounds__(512)
k_fused(const float* __restrict__ x,
        const float* __restrict__ c0, const float* __restrict__ c1,
        const float* __restrict__ c2, const float* __restrict__ c3,
        const float* __restrict__ bias, float* __restrict__ out)
{
    extern __shared__ char smem[];
    const uint32_t sbu = s2u(smem);
    const int tid  = threadIdx.x;
    const int lane = tid & 31;
    const int w    = tid >> 5;                          // 0..15
    const int quad = lane >> 3, lr = lane & 7;
    const int b0   = blockIdx.x * 64;

    // ---- build P_s[(m01*8+r2)][n01] (fp16, SW 64B rows) from c0,c1 ----
    // f-index n = n0*256+n1*32+n2*4+n3 ; o-index m = m0*512+m1*64+m2*8+m3
#pragma unroll
    for (int i = 0; i < 32; ++i) {
        int idx = tid + i * 512;                        // 16384 = 512 rows x 32
        int n01 = idx & 31, row = idx >> 5;             // row = m01*8 + r2
        int r2 = row & 7, m01 = row >> 3;
        int m0 = m01 >> 3, m1 = m01 & 7, n0 = n01 >> 3, n1 = n01 & 7;
        float s = 0.f;
#pragma unroll
        for (int r1 = 0; r1 < 8; ++r1)
            s = fmaf(c0[m0 * 32 + r1 * 4 + n0], c1[r1 * 512 + m1 * 64 + r2 * 8 + n1], s);
        *(__half*)(smem + P_OFF + SW((uint32_t)(row * 64 + n01 * 2))) = __float2half_rn(s);
    }

    // ---- build Q_s[kc][m23][k&31] (fp16, SW 64B rows per chunk) from c2,c3 ----
#pragma unroll
    for (int i = 0; i < 32; ++i) {
        int idx = tid + i * 512;                        // 16384 = 64 m23 x 256 k
        int k = idx & 255, m23 = idx >> 8;              // k = n23*8 + r2
        int r2 = k & 7, n23 = k >> 3;
        int m2 = m23 >> 3, m3 = m23 & 7, n2 = n23 >> 2, n3 = n23 & 3;
        float s = 0.f;
#pragma unroll
        for (int r3 = 0; r3 < 8; ++r3)
            s = fmaf(c2[r2 * 512 + m2 * 64 + r3 * 8 + n2], c3[r3 * 32 + m3 * 4 + n3], s);
        *(__half*)(smem + Q_OFF + (uint32_t)((k >> 5) * 4096)
                   + SW((uint32_t)(m23 * 64 + (k & 31) * 2))) = __float2half_rn(s);
    }

    // ---- load + transpose x slice: xT rows R = n23*64 + b(local), cols n01 ----
    {
        const float4* x4 = (const float4*)x;
        const int row = tid >> 3;                       // local b, 0..63
        const int qb  = tid & 7;
#pragma unroll
        for (int i = 0; i < 32; ++i) {
            int q = qb + i * 8;                         // 0..255 float4 in row
            float4 f = x4[(size_t)(b0 + row) * 256 + q];
            int n01 = q >> 3;
            int n23b = (q & 7) * 4;
            float v[4] = { f.x, f.y, f.z, f.w };
#pragma unroll
            for (int j = 0; j < 4; ++j) {
                uint32_t R = (uint32_t)((n23b + j) * 64 + row);
                *(__half*)(smem + XT_OFF + SW(R * 64u + (uint32_t)(n01 * 2)))
                    = __float2half_rn(v[j]);
            }
        }
    }
    __syncthreads();

    // stage2 warp grid: 4(b) x 4(m23), warp tile 16x16
    const int wm2 = w >> 2, wn2 = w & 3;

    for (int m01 = 0; m01 < 64; ++m01) {
        // ---- stage1: Zs[b][k] for this m01 ----
        uint32_t bf1[2][4];
#pragma unroll
        for (int kk = 0; kk < 2; ++kk)
            ldm_x4(bf1[kk], sbu + P_OFF
                   + SW((uint32_t)((m01 * 8 + ((quad >> 1) & 1) * 8 + lr) * 64
                                   + kk * 32 + (quad & 1) * 16)));
#pragma unroll
        for (int mt = 0; mt < 8; ++mt) {
            float acc[4] = {0.f, 0.f, 0.f, 0.f};
#pragma unroll
            for (int kk = 0; kk < 2; ++kk) {
                uint32_t af[4];
                ldm_x4(af, sbu + XT_OFF
                       + SW((uint32_t)((w * 128 + mt * 16 + (quad & 1) * 8 + lr) * 64
                                       + kk * 32 + ((quad >> 1) & 1) * 16)));
                mma16816(acc, af, bf1[kk]);
            }
#pragma unroll
            for (int half = 0; half < 2; ++half) {
                int R = w * 128 + mt * 16 + (lane >> 2) + half * 8;
                int bl = R & 63, n23 = R >> 6;
                uint32_t addr = Z_OFF + (uint32_t)((n23 >> 2) * 4096)
                    + SW((uint32_t)(bl * 64 + (n23 & 3) * 16 + (lane & 3) * 4));
                __half2 v = __floats2half2_rn(acc[half * 2], acc[half * 2 + 1]);
                *(uint32_t*)(smem + addr) = h2u(v);
            }
        }
        __syncthreads();                                // Zs ready

        // ---- stage2: y[64 x 64] for this m01 ----
        float d2[2][4];
#pragma unroll
        for (int i = 0; i < 2; ++i)
#pragma unroll
            for (int q = 0; q < 4; ++q) d2[i][q] = 0.f;

#pragma unroll
        for (int kc = 0; kc < 8; ++kc) {
#pragma unroll
            for (int kkl = 0; kkl < 2; ++kkl) {
                uint32_t af[4], bf[4];
                ldm_x4(af, sbu + Z_OFF + (uint32_t)(kc * 4096)
                       + SW((uint32_t)((wm2 * 16 + (quad & 1) * 8 + lr) * 64
                                       + kkl * 32 + ((quad >> 1) & 1) * 16)));
                ldm_x4(bf, sbu + Q_OFF + (uint32_t)(kc * 4096)
                       + SW((uint32_t)((wn2 * 16 + ((quad >> 1) & 1) * 8 + lr) * 64
                                       + kkl * 32 + (quad & 1) * 16)));
                mma16816(d2[0], af, &bf[0]);
                mma16816(d2[1], af, &bf[2]);
            }
        }

        // ---- epilogue: +bias, write fp32 ----
        const int erow = b0 + wm2 * 16 + (lane >> 2);
        const int ecol = m01 * 64 + wn2 * 16 + (lane & 3) * 2;
#pragma unroll
        for (int nt = 0; nt < 2; ++nt) {
            float bx = __ldg(bias + ecol + nt * 8);
            float by = __ldg(bias + ecol + nt * 8 + 1);
            float* r0 = out + (size_t)erow * OUTF + ecol + nt * 8;
            float* r1 = r0 + 8 * OUTF;
            float2 v0 = { d2[nt][0] + bx, d2[nt][1] + by };
            float2 v1 = { d2[nt][2] + bx, d2[nt][3] + by };
            *reinterpret_cast<float2*>(r0) = v0;
            *reinterpret_cast<float2*>(r1) = v1;
        }
        __syncthreads();                                // Zs reusable
    }
}

// ============================================================================
extern "C" void kernel_launch(void* const* d_in, const int* in_sizes, int n_in,
                              void* d_out, int out_size)
{
    const float* x    = (const float*)d_in[0];
    const float* c0   = (const float*)d_in[1];
    const float* c1   = (const float*)d_in[2];
    const float* c2   = (const float*)d_in[3];
    const float* c3   = (const float*)d_in[4];
    const float* bias = (const float*)d_in[5];
    float* out = (float*)d_out;

    cudaFuncSetAttribute(k_fused, cudaFuncAttributeMaxDynamicSharedMemorySize,
                         SMEM_TOTAL);
    k_fused<<<128, 512, SMEM_TOTAL>>>(x, c0, c1, c2, c3, bias, out);
}

// round 10
// speedup vs baseline: 2.7891x; 2.7891x over previous
#include <cuda_runtime.h>
#include <cuda_fp16.h>
#include <cstdint>
#include <cstddef>
#include <cstring>

// ============================================================================
// TTLinear, fully fused single launch (R10):
//   CTA = 64-row b-block. xT (fp16, whole 64x1024 slice) is loaded ONCE into
//   per-thread registers (128 regs) as stage-1 A fragments. Loop over 64 m01
//   planes, 2 per iteration:
//     stage1: Zs[bl][k=n23*8+r2] = xT x P(m01)      (smem, double-buffered)
//     stage2: y[bl][m01*64+m23] += Zs x Q^T + bias  (32x32 warp tiles)
//   P/Q rebuilt per CTA from TT cores (trivial). One __syncthreads per iter.
// ============================================================================

#define OUTF 4096
#define P_OFF  0u
#define Q_OFF  32768u
#define ZX_OFF 65536u              // xT overlay; then two 64KB Z buffers
#define SMEM_TOTAL 196608

#define SW(o) ((o) ^ ((((o) >> 7) & 3u) << 4))

static __device__ __forceinline__ uint32_t h2u(__half2 h) {
    uint32_t u; memcpy(&u, &h, 4); return u;
}
static __device__ __forceinline__ uint32_t s2u(const void* p) {
    uint32_t a;
    asm("{ .reg .u64 t; cvta.to.shared.u64 t, %1; cvt.u32.u64 %0, t; }" : "=r"(a) : "l"(p));
    return a;
}
// 512B-row layout with per-row XOR swizzle (conflict-free STS + ldmatrix)
static __device__ __forceinline__ uint32_t zsw(int row, uint32_t off) {
    return (uint32_t)(row * 512) + (off ^ (((uint32_t)row & 7u) << 4));
}
static __device__ __forceinline__ void ldm_x4(uint32_t* r, uint32_t addr) {
    asm volatile("ldmatrix.sync.aligned.m8n8.x4.shared.b16 {%0,%1,%2,%3}, [%4];"
                 : "=r"(r[0]), "=r"(r[1]), "=r"(r[2]), "=r"(r[3]) : "r"(addr));
}
static __device__ __forceinline__ void mma16816(float* d, const uint32_t* a,
                                                const uint32_t* b) {
    asm volatile(
        "mma.sync.aligned.m16n8k16.row.col.f32.f16.f16.f32 "
        "{%0,%1,%2,%3}, {%4,%5,%6,%7}, {%8,%9}, {%0,%1,%2,%3};"
        : "+f"(d[0]), "+f"(d[1]), "+f"(d[2]), "+f"(d[3])
        : "r"(a[0]), "r"(a[1]), "r"(a[2]), "r"(a[3]), "r"(b[0]), "r"(b[1]));
}

__global__ void __launch_bounds__(256, 1)
k_fused(const float* __restrict__ x,
        const float* __restrict__ c0, const float* __restrict__ c1,
        const float* __restrict__ c2, const float* __restrict__ c3,
        const float* __restrict__ bias, float* __restrict__ out)
{
    extern __shared__ char smem[];
    const uint32_t sbu = s2u(smem);
    const int tid  = threadIdx.x;
    const int lane = tid & 31;
    const int w    = tid >> 5;                      // 0..7
    const int quad = lane >> 3, lr = lane & 7;
    const int wm2  = w >> 2;                        // 0..1: b half (32 rows)
    const int wn2  = w & 3;                         // 0..3: col group of 32
    const int b0   = blockIdx.x * 64;

    // ---- build P[(m01*8+r2)][n01] fp16, 64B SW rows ----
    // n = n0*256+n1*32+n2*4+n3 ; m = m0*512+m1*64+m2*8+m3
#pragma unroll
    for (int i = 0; i < 64; ++i) {
        int idx = tid + i * 256;                    // 16384
        int n01 = idx & 31, row = idx >> 5;         // row = m01*8+r2
        int r2 = row & 7, m01 = row >> 3;
        int m0 = m01 >> 3, m1 = m01 & 7, n0 = n01 >> 3, n1 = n01 & 7;
        float s = 0.f;
#pragma unroll
        for (int r1 = 0; r1 < 8; ++r1)
            s = fmaf(c0[m0 * 32 + r1 * 4 + n0], c1[r1 * 512 + m1 * 64 + r2 * 8 + n1], s);
        *(__half*)(smem + P_OFF + SW((uint32_t)(row * 64 + n01 * 2))) = __float2half_rn(s);
    }
    // ---- build Q[m23][k=n23*8+r2] fp16, 512B zsw rows ----
#pragma unroll
    for (int i = 0; i < 64; ++i) {
        int idx = tid + i * 256;                    // 16384
        int k = idx & 255, m23 = idx >> 8;
        int r2 = k & 7, n23 = k >> 3;
        int m2 = m23 >> 3, m3 = m23 & 7, n2 = n23 >> 2, n3 = n23 & 3;
        float s = 0.f;
#pragma unroll
        for (int r3 = 0; r3 < 8; ++r3)
            s = fmaf(c2[r2 * 512 + m2 * 64 + r3 * 8 + n2], c3[r3 * 32 + m3 * 4 + n3], s);
        *(__half*)(smem + Q_OFF + zsw(m23, (uint32_t)(k * 2))) = __float2half_rn(s);
    }
    // ---- xT fill: rows R = n23*64 + bl (2048 x 64B SW), overlaid on Z bufs ----
    {
        const float4* x4 = (const float4*)x;
        const int row = tid >> 2;                   // local b, 0..63
        const int qb  = tid & 3;
#pragma unroll
        for (int i = 0; i < 64; ++i) {
            int q = qb + i * 4;                     // 0..255
            float4 f = x4[(size_t)(b0 + row) * 256 + q];
            int n01 = q >> 3;
            int n23b = (q & 7) * 4;
            float v[4] = { f.x, f.y, f.z, f.w };
#pragma unroll
            for (int j = 0; j < 4; ++j) {
                uint32_t R = (uint32_t)((n23b + j) * 64 + row);
                *(__half*)(smem + ZX_OFF + SW(R * 64u + (uint32_t)(n01 * 2)))
                    = __float2half_rn(v[j]);
            }
        }
    }
    __syncthreads();

    // ---- stage-1 A cache: whole xT -> registers (16 mt x 2 kk x 4) ----
    uint32_t ac[16][2][4];
#pragma unroll
    for (int mt = 0; mt < 16; ++mt)
#pragma unroll
        for (int kk = 0; kk < 2; ++kk)
            ldm_x4(ac[mt][kk], sbu + ZX_OFF
                   + SW((uint32_t)((w * 256 + mt * 16 + (quad & 1) * 8 + lr) * 64
                                   + kk * 32 + ((quad >> 1) & 1) * 16)));
    __syncthreads();                                // xT fully consumed

    float d2[2][4][4];
#pragma unroll
    for (int i = 0; i < 2; ++i)
#pragma unroll
        for (int j = 0; j < 4; ++j)
#pragma unroll
            for (int q = 0; q < 4; ++q) d2[i][j][q] = 0.f;

    const int plane_sel = wn2 >> 1;                 // which of the 2 planes
    const int s2brow = wm2 * 32;                    // stage2 A row base

    // stage1 of iteration `it` (2 planes) into Z buffer it&1
    auto stage1 = [&](int it) {
        uint32_t zb = ZX_OFF + (uint32_t)((it & 1) * 65536);
#pragma unroll
        for (int pp = 0; pp < 2; ++pp) {
            int m01 = it * 2 + pp;
            uint32_t bfP[4];
            ldm_x4(bfP, sbu + P_OFF + SW((uint32_t)((m01 * 8 + lr) * 64 + quad * 16)));
            uint32_t zpb = zb + (uint32_t)(pp * 32768);
#pragma unroll
            for (int mt = 0; mt < 16; ++mt) {
                float acc[4] = {0.f, 0.f, 0.f, 0.f};
                mma16816(acc, ac[mt][0], &bfP[0]);
                mma16816(acc, ac[mt][1], &bfP[2]);
                int Rb = w * 256 + mt * 16 + (lane >> 2);
#pragma unroll
                for (int half = 0; half < 2; ++half) {
                    int R = Rb + half * 8;
                    int n23 = R >> 6, bl = R & 63;
                    __half2 v = __floats2half2_rn(acc[half * 2], acc[half * 2 + 1]);
                    *(uint32_t*)(smem + zpb
                        + zsw(bl, (uint32_t)(n23 * 16 + (lane & 3) * 4))) = h2u(v);
                }
            }
        }
    };

    stage1(0);
    for (int it = 0; it < 32; ++it) {
        __syncthreads();                            // Z[it&1] visible
        if (it + 1 < 32) stage1(it + 1);            // fill other buffer

        // ---- stage2: y[64 x 128] from Z[it&1] (2 planes) ----
        const uint32_t za = sbu + ZX_OFF + (uint32_t)((it & 1) * 65536)
                          + (uint32_t)(plane_sel * 32768);
#pragma unroll
        for (int ks = 0; ks < 16; ++ks) {
            uint32_t a[2][4], bq[2][4];
#pragma unroll
            for (int mt = 0; mt < 2; ++mt)
                ldm_x4(a[mt], za + zsw(s2brow + mt * 16 + (lane & 15),
                                       (uint32_t)(ks * 32 + (lane >> 4) * 16)));
#pragma unroll
            for (int nt = 0; nt < 2; ++nt)
                ldm_x4(bq[nt], sbu + Q_OFF
                       + zsw((wn2 & 1) * 32 + nt * 16 + ((quad >> 1) & 1) * 8 + lr,
                             (uint32_t)(ks * 32 + (quad & 1) * 16)));
#pragma unroll
            for (int mt = 0; mt < 2; ++mt)
#pragma unroll
                for (int nt = 0; nt < 2; ++nt) {
                    mma16816(d2[mt][nt * 2],     a[mt], &bq[nt][0]);
                    mma16816(d2[mt][nt * 2 + 1], a[mt], &bq[nt][2]);
                }
        }

        // ---- epilogue for this iteration's plane ----
        const int m01 = it * 2 + plane_sel;
        const int erow  = b0 + s2brow + (lane >> 2);
        const int ecolb = m01 * 64 + (wn2 & 1) * 32 + (lane & 3) * 2;
#pragma unroll
        for (int mt = 0; mt < 2; ++mt) {
#pragma unroll
            for (int nt = 0; nt < 2; ++nt) {
#pragma unroll
                for (int p = 0; p < 2; ++p) {
                    int col = ecolb + nt * 16 + p * 8;
                    float bx = __ldg(bias + col);
                    float by = __ldg(bias + col + 1);
                    float* r0 = out + (size_t)(erow + mt * 16) * OUTF + col;
                    float* r1 = r0 + 8 * OUTF;
                    float* dd = d2[mt][nt * 2 + p];
                    float2 v0 = { dd[0] + bx, dd[1] + by };
                    float2 v1 = { dd[2] + bx, dd[3] + by };
                    *reinterpret_cast<float2*>(r0) = v0;
                    *reinterpret_cast<float2*>(r1) = v1;
                    dd[0] = dd[1] = dd[2] = dd[3] = 0.f;
                }
            }
        }
    }
}

// ============================================================================
extern "C" void kernel_launch(void* const* d_in, const int* in_sizes, int n_in,
                              void* d_out, int out_size)
{
    const float* x    = (const float*)d_in[0];
    const float* c0   = (const float*)d_in[1];
    const float* c1   = (const float*)d_in[2];
    const float* c2   = (const float*)d_in[3];
    const float* c3   = (const float*)d_in[4];
    const float* bias = (const float*)d_in[5];
    float* out = (float*)d_out;

    cudaFuncSetAttribute(k_fused, cudaFuncAttributeMaxDynamicSharedMemorySize,
                         SMEM_TOTAL);
    k_fused<<<128, 256, SMEM_TOTAL>>>(x, c0, c1, c2, c3, bias, out);
}